// round 11
// baseline (speedup 1.0000x reference)
#include <cuda_runtime.h>
#include <cuda_bf16.h>
#include <math_constants.h>
#include <cstdint>

// Shapes (fixed by the problem)
#define VOCAB   100000
#define DIM     300
#define BATCH   4096
#define SEQ     200
#define KDIM    600      // 2*DIM
#define HIDDEN  1000
#define OUTD    3

// Split-bf16 GEMM1 geometry
#define KP      1824     // padded K' = 3*600 -> 1824 (57 x 32)
#define KC      32       // K elems per SMEM stage
#define NSTAGES (KP / KC)   // 57
#define BM      128
#define BN      128
#define NPAD    1024     // padded N (8 x 128)
#define NTILES  (NPAD / BN)  // 8
#define SKP     40       // smem row stride in bf16 (32 + 8 pad) -> conflict-free ldmatrix
#define STG     4        // cp.async pipeline depth
#define TILE_E  (BM * SKP)            // bf16 elems per stage per matrix (5120)
#define SMEM_MAIN (2 * STG * TILE_E * 2)   // As+Bs bytes (81920)
#define SMEM_RED  (4 * BM * OUTD * 4)      // s_red bytes (6144)
#define SMEM_DYN  (SMEM_MAIN + SMEM_RED)   // 88064

// Scratch (device globals: no allocations allowed)
__device__ __align__(16) __nv_bfloat16 g_A [BATCH * KP];   // [4096,1824] A' = [Ahi|Ahi|Alo]
__device__ __align__(16) __nv_bfloat16 g_Wt[NPAD * KP];    // [1024,1824] W' = [Whi|Wlo|Whi] (K-major)
__device__ __align__(16) float g_part[NTILES * BATCH * OUTD];  // fused-gemm2 partials

typedef unsigned long long ull;

// ===========================================================================
// Small PTX helpers
// ===========================================================================
__device__ __forceinline__ uint32_t smem_u32(const void* p) {
    uint32_t a;
    asm("{ .reg .u64 t; cvta.to.shared.u64 t, %1; cvt.u32.u64 %0, t; }" : "=r"(a) : "l"(p));
    return a;
}
__device__ __forceinline__ void ldsm_x4(uint32_t& r0, uint32_t& r1, uint32_t& r2,
                                        uint32_t& r3, uint32_t addr) {
    asm volatile("ldmatrix.sync.aligned.m8n8.x4.shared.b16 {%0,%1,%2,%3}, [%4];"
                 : "=r"(r0), "=r"(r1), "=r"(r2), "=r"(r3) : "r"(addr));
}
__device__ __forceinline__ void mma_bf16(float& c0, float& c1, float& c2, float& c3,
                                         uint32_t a0, uint32_t a1, uint32_t a2, uint32_t a3,
                                         uint32_t b0, uint32_t b1) {
    asm volatile("mma.sync.aligned.m16n8k16.row.col.f32.bf16.bf16.f32 "
                 "{%0,%1,%2,%3}, {%4,%5,%6,%7}, {%8,%9}, {%0,%1,%2,%3};"
                 : "+f"(c0), "+f"(c1), "+f"(c2), "+f"(c3)
                 : "r"(a0), "r"(a1), "r"(a2), "r"(a3), "r"(b0), "r"(b1));
}
__device__ __forceinline__ void cp_async16(uint32_t dst, const void* src) {
    asm volatile("cp.async.cg.shared.global [%0], [%1], 16;"
                 :: "r"(dst), "l"(src) : "memory");
}
__device__ __forceinline__ void cp_commit() {
    asm volatile("cp.async.commit_group;" ::: "memory");
}
template<int N>
__device__ __forceinline__ void cp_wait() {
    asm volatile("cp.async.wait_group %0;" :: "n"(N) : "memory");
}

// ===========================================================================
// Pool (gather + mean/max) fused with A' bf16 hi/lo emission
// ===========================================================================
__device__ __forceinline__ ull mk_evict_last_policy() {
    ull pol;
    asm("createpolicy.fractional.L2::evict_last.b64 %0, 1.0;" : "=l"(pol));
    return pol;
}
__device__ __forceinline__ float4 ldg_el(const float4* p, ull pol) {
    float4 v;
    asm("ld.global.nc.L2::cache_hint.v4.f32 {%0,%1,%2,%3}, [%4], %5;"
        : "=f"(v.x), "=f"(v.y), "=f"(v.z), "=f"(v.w) : "l"(p), "l"(pol));
    return v;
}

// write 4 floats at A'[row][k..k+3] in hi/hi/lo form
__device__ __forceinline__ void store_hilo4(size_t rowb, int k, float4 v) {
    __nv_bfloat16 h0 = __float2bfloat16(v.x), h1 = __float2bfloat16(v.y);
    __nv_bfloat16 h2 = __float2bfloat16(v.z), h3 = __float2bfloat16(v.w);
    __nv_bfloat16 l0 = __float2bfloat16(v.x - __bfloat162float(h0));
    __nv_bfloat16 l1 = __float2bfloat16(v.y - __bfloat162float(h1));
    __nv_bfloat16 l2 = __float2bfloat16(v.z - __bfloat162float(h2));
    __nv_bfloat16 l3 = __float2bfloat16(v.w - __bfloat162float(h3));
    __nv_bfloat162 hA = __halves2bfloat162(h0, h1), hB = __halves2bfloat162(h2, h3);
    __nv_bfloat162 lA = __halves2bfloat162(l0, l1), lB = __halves2bfloat162(l2, l3);
    *(__nv_bfloat162*)&g_A[rowb + k]             = hA;
    *(__nv_bfloat162*)&g_A[rowb + k + 2]         = hB;
    *(__nv_bfloat162*)&g_A[rowb + 600 + k]       = hA;
    *(__nv_bfloat162*)&g_A[rowb + 600 + k + 2]   = hB;
    *(__nv_bfloat162*)&g_A[rowb + 1200 + k]      = lA;
    *(__nv_bfloat162*)&g_A[rowb + 1200 + k + 2]  = lB;
}

#define D4 (DIM / 4)            // 75 float4 per row
#define POOL_T 160

__global__ __launch_bounds__(POOL_T) void pool_kernel(
    const float* __restrict__ emb,
    const int*   __restrict__ x,
    const int*   __restrict__ lengths)
{
    __shared__ int    sidx[SEQ];
    __shared__ int    slen;
    __shared__ float4 s_sum[2][D4];
    __shared__ float4 s_max[2][D4];

    const int b   = blockIdx.x;
    const int tid = threadIdx.x;

    for (int i = tid; i < SEQ; i += POOL_T) sidx[i] = x[b * SEQ + i];
    if (tid == 0) slen = lengths[b];
    __syncthreads();

    const int len  = slen;
    const int g    = tid / 80;
    const int lane = tid % 80;
    const float NEG_INF = __int_as_float(0xff800000);

    if (lane < D4) {
        const ull pol = mk_evict_last_policy();
        const float4* base = (const float4*)emb + lane;
        float4 sum = make_float4(0.f, 0.f, 0.f, 0.f);
        float4 mx  = make_float4(NEG_INF, NEG_INF, NEG_INF, NEG_INF);
        const int l0 = g * 100;
        #pragma unroll 4
        for (int l = 0; l < 100; ++l) {
            const int tok = l0 + l;
            float4 v = ldg_el(base + (size_t)sidx[tok] * D4, pol);
            sum.x += v.x; sum.y += v.y; sum.z += v.z; sum.w += v.w;
            if (tok < len) {
                mx.x = fmaxf(mx.x, v.x); mx.y = fmaxf(mx.y, v.y);
                mx.z = fmaxf(mx.z, v.z); mx.w = fmaxf(mx.w, v.w);
            }
        }
        s_sum[g][lane] = sum;
        s_max[g][lane] = mx;
    }
    __syncthreads();

    const size_t rowb = (size_t)b * KP;
    if (tid < D4) {
        float4 s0 = s_sum[0][tid], s1 = s_sum[1][tid];
        float4 m0 = s_max[0][tid], m1 = s_max[1][tid];
        const float inv = 1.0f / (float)len;
        float4 mean = make_float4((s0.x + s1.x) * inv, (s0.y + s1.y) * inv,
                                  (s0.z + s1.z) * inv, (s0.w + s1.w) * inv);
        float4 mx   = make_float4(fmaxf(m0.x, m1.x), fmaxf(m0.y, m1.y),
                                  fmaxf(m0.z, m1.z), fmaxf(m0.w, m1.w));
        store_hilo4(rowb, 4 * tid, mean);            // k' = d
        store_hilo4(rowb, DIM + 4 * tid, mx);        // k' = 300 + d
    }
    // zero-pad K' [1800,1824)
    if (tid >= 80 && tid < 92) {
        const int k = 1800 + (tid - 80) * 2;
        *(__nv_bfloat162*)&g_A[rowb + k] =
            __halves2bfloat162(__float2bfloat16(0.f), __float2bfloat16(0.f));
    }
}

// ===========================================================================
// W' prep: g_Wt[n][k'] K-major, [Whi | Wlo | Whi], rows n>=1000 zero
// ===========================================================================
__global__ __launch_bounds__(256) void wprep_kernel(const float* __restrict__ W1)
{
    const int n = blockIdx.x;                 // 0..1023
    __nv_bfloat16* dst = &g_Wt[(size_t)n * KP];
    for (int k = threadIdx.x; k < KP; k += 256) {
        __nv_bfloat16 o = __float2bfloat16(0.f);
        if (n < HIDDEN) {
            if (k < 600) {
                o = __float2bfloat16(W1[(size_t)k * HIDDEN + n]);
            } else if (k < 1200) {
                float v = W1[(size_t)(k - 600) * HIDDEN + n];
                __nv_bfloat16 h = __float2bfloat16(v);
                o = __float2bfloat16(v - __bfloat162float(h));
            } else if (k < 1800) {
                o = __float2bfloat16(W1[(size_t)(k - 1200) * HIDDEN + n]);
            }
        }
        dst[k] = o;
    }
}

// ===========================================================================
// GEMM1 (fused): partial_out = relu(A' @ W'^T + b1) @ W2, per N-tile.
// 128x128 block, 8 warps (2M x 4N), cp.async 4-stage pipeline, KC=32.
// h never hits global memory.
// ===========================================================================
__global__ __launch_bounds__(256) void gemm1_fused_kernel(
    const float* __restrict__ b1,
    const float* __restrict__ W2)
{
    extern __shared__ __align__(16) unsigned char smem[];
    __nv_bfloat16* As = (__nv_bfloat16*)smem;                 // [STG][BM][SKP]
    __nv_bfloat16* Bs = As + STG * TILE_E;                    // [STG][BN][SKP]
    float* s_red = (float*)(smem + SMEM_MAIN);                // [4][BM][OUTD]

    const int tid  = threadIdx.x;
    const int warp = tid >> 5;
    const int lane = tid & 31;
    const int wm   = warp >> 2;       // 0..1
    const int wn   = warp & 3;        // 0..3
    const int block_row = blockIdx.x * BM;
    const int block_col = blockIdx.y * BN;

    // Global-load mapping: per tile 128 rows x 32 k = 512 x 16B; 2 per thread per matrix.
    const int r0 = (tid >> 2);            // row (u=0); u=1 -> +64
    const int c0 = (tid & 3) * 8;         // bf16 col

    const __nv_bfloat16* gA0 = &g_A [(size_t)(block_row + r0)      * KP + c0];
    const __nv_bfloat16* gA1 = &g_A [(size_t)(block_row + r0 + 64) * KP + c0];
    const __nv_bfloat16* gB0 = &g_Wt[(size_t)(block_col + r0)      * KP + c0];
    const __nv_bfloat16* gB1 = &g_Wt[(size_t)(block_col + r0 + 64) * KP + c0];

    // smem dst addresses (stage 0; add st*TILE_E*2 bytes)
    const uint32_t dA0 = smem_u32(As + r0 * SKP + c0);
    const uint32_t dA1 = smem_u32(As + (r0 + 64) * SKP + c0);
    const uint32_t dB0 = smem_u32(Bs + r0 * SKP + c0);
    const uint32_t dB1 = smem_u32(Bs + (r0 + 64) * SKP + c0);

    // ldmatrix per-lane coordinates
    const int a_m = lane & 15;                          // row within 16
    const int a_k = (lane >> 4) << 3;                   // 0 or 8
    const int b_n = ((lane >> 4) << 3) + (lane & 7);    // row within 16 (n)
    const int b_k = lane & 8;                           // 0 or 8

    float acc[4][4][4];
    #pragma unroll
    for (int i = 0; i < 4; ++i)
        #pragma unroll
        for (int j = 0; j < 4; ++j)
            #pragma unroll
            for (int e = 0; e < 4; ++e) acc[i][j][e] = 0.0f;

    // Prologue: fill stages 0..STG-2
    #pragma unroll
    for (int st = 0; st < STG - 1; ++st) {
        const size_t koff = (size_t)st * KC;
        const uint32_t so = st * (TILE_E * 2);
        cp_async16(dA0 + so, gA0 + koff);
        cp_async16(dA1 + so, gA1 + koff);
        cp_async16(dB0 + so, gB0 + koff);
        cp_async16(dB1 + so, gB1 + koff);
        cp_commit();
    }

    for (int s = 0; s < NSTAGES; ++s) {
        cp_wait<STG - 2>();
        __syncthreads();

        // prefetch stage s + STG-1
        if (s + STG - 1 < NSTAGES) {
            const size_t koff = (size_t)(s + STG - 1) * KC;
            const uint32_t so = ((s + STG - 1) & (STG - 1)) * (TILE_E * 2);
            cp_async16(dA0 + so, gA0 + koff);
            cp_async16(dA1 + so, gA1 + koff);
            cp_async16(dB0 + so, gB0 + koff);
            cp_async16(dB1 + so, gB1 + koff);
        }
        cp_commit();

        const int buf = s & (STG - 1);
        const __nv_bfloat16* Ab = As + buf * TILE_E;
        const __nv_bfloat16* Bb = Bs + buf * TILE_E;

        #pragma unroll
        for (int q = 0; q < 2; ++q) {                 // two k16 steps
            const int kq = q * 16;
            uint32_t a[4][4];
            #pragma unroll
            for (int i = 0; i < 4; ++i) {
                const uint32_t addr = smem_u32(
                    Ab + (wm * 64 + i * 16 + a_m) * SKP + kq + a_k);
                ldsm_x4(a[i][0], a[i][1], a[i][2], a[i][3], addr);
            }
            uint32_t bfr[4][2];
            #pragma unroll
            for (int p = 0; p < 2; ++p) {             // pairs of n8 tiles
                const uint32_t addr = smem_u32(
                    Bb + (wn * 32 + p * 16 + b_n) * SKP + kq + b_k);
                uint32_t t0, t1, t2, t3;
                ldsm_x4(t0, t1, t2, t3, addr);
                bfr[p * 2 + 0][0] = t0; bfr[p * 2 + 0][1] = t1;
                bfr[p * 2 + 1][0] = t2; bfr[p * 2 + 1][1] = t3;
            }
            #pragma unroll
            for (int i = 0; i < 4; ++i)
                #pragma unroll
                for (int j = 0; j < 4; ++j)
                    mma_bf16(acc[i][j][0], acc[i][j][1], acc[i][j][2], acc[i][j][3],
                             a[i][0], a[i][1], a[i][2], a[i][3],
                             bfr[j][0], bfr[j][1]);
        }
        __syncthreads();
    }

    // ---- Fused epilogue: p[m][c] = sum_n relu(acc + b1[n]) * W2[n][c] ----
    const int mq = lane >> 2;            // 0..7
    const int nq = (lane & 3) * 2;       // 0,2,4,6

    float part[8][OUTD];                 // r = i*2 + e_hi -> m rows
    #pragma unroll
    for (int r = 0; r < 8; ++r)
        #pragma unroll
        for (int c = 0; c < OUTD; ++c) part[r][c] = 0.0f;

    #pragma unroll
    for (int j = 0; j < 4; ++j) {
        const int n0 = block_col + wn * 32 + j * 8 + nq;   // even; n1 = n0+1
        float bn0 = 0.f, bn1 = 0.f;
        float w0[OUTD] = {0.f, 0.f, 0.f}, w1[OUTD] = {0.f, 0.f, 0.f};
        if (n0 < HIDDEN) {
            bn0 = b1[n0]; bn1 = b1[n0 + 1];
            #pragma unroll
            for (int c = 0; c < OUTD; ++c) {
                w0[c] = W2[n0 * OUTD + c];
                w1[c] = W2[(n0 + 1) * OUTD + c];
            }
        }
        #pragma unroll
        for (int i = 0; i < 4; ++i) {
            const float h00 = fmaxf(acc[i][j][0] + bn0, 0.0f);
            const float h01 = fmaxf(acc[i][j][1] + bn1, 0.0f);
            const float h10 = fmaxf(acc[i][j][2] + bn0, 0.0f);
            const float h11 = fmaxf(acc[i][j][3] + bn1, 0.0f);
            #pragma unroll
            for (int c = 0; c < OUTD; ++c) {
                part[i * 2 + 0][c] = fmaf(h00, w0[c], fmaf(h01, w1[c], part[i * 2 + 0][c]));
                part[i * 2 + 1][c] = fmaf(h10, w0[c], fmaf(h11, w1[c], part[i * 2 + 1][c]));
            }
        }
    }

    // reduce across the 4 lanes (nq groups) sharing each m-row (deterministic)
    #pragma unroll
    for (int r = 0; r < 8; ++r)
        #pragma unroll
        for (int c = 0; c < OUTD; ++c) {
            float v = part[r][c];
            v += __shfl_xor_sync(0xFFFFFFFFu, v, 1);
            v += __shfl_xor_sync(0xFFFFFFFFu, v, 2);
            part[r][c] = v;
        }

    if ((lane & 3) == 0) {
        #pragma unroll
        for (int r = 0; r < 8; ++r) {
            const int row = wm * 64 + (r >> 1) * 16 + mq + (r & 1) * 8;
            #pragma unroll
            for (int c = 0; c < OUTD; ++c)
                s_red[(wn * BM + row) * OUTD + c] = part[r][c];
        }
    }
    __syncthreads();

    // sum the 4 wn slices; one (row, c) per thread
    for (int idx = tid; idx < BM * OUTD; idx += 256) {
        const int row = idx / OUTD, c = idx % OUTD;
        const float v = s_red[(0 * BM + row) * OUTD + c] + s_red[(1 * BM + row) * OUTD + c]
                      + s_red[(2 * BM + row) * OUTD + c] + s_red[(3 * BM + row) * OUTD + c];
        g_part[((size_t)blockIdx.y * BATCH + (block_row + row)) * OUTD + c] = v;
    }
}

// ===========================================================================
// Final reduce: out[m][c] = b2[c] + sum_z g_part[z][m][c]   (fixed order)
// One scalar per thread, fully coalesced. 12288 scalars -> 48 blocks.
// ===========================================================================
__global__ __launch_bounds__(256) void out_reduce_kernel(
    const float* __restrict__ b2,
    float* __restrict__ out)
{
    const int idx = blockIdx.x * 256 + threadIdx.x;   // m*3 + c
    float a = b2[idx % OUTD];
    #pragma unroll
    for (int z = 0; z < NTILES; ++z)
        a += g_part[(size_t)z * (BATCH * OUTD) + idx];
    out[idx] = a;
}

// ===========================================================================
// Launch. Input order (metadata): emb_table, W1, b1, W2, b2, x, lengths.
// ===========================================================================
extern "C" void kernel_launch(void* const* d_in, const int* in_sizes, int n_in,
                              void* d_out, int out_size)
{
    const float* emb     = (const float*)d_in[0];
    const float* W1      = (const float*)d_in[1];
    const float* b1      = (const float*)d_in[2];
    const float* W2      = (const float*)d_in[3];
    const float* b2      = (const float*)d_in[4];
    const int*   x       = (const int*)  d_in[5];
    const int*   lengths = (const int*)  d_in[6];
    float*       out     = (float*)d_out;

    cudaFuncSetAttribute(gemm1_fused_kernel,
                         cudaFuncAttributeMaxDynamicSharedMemorySize, SMEM_DYN);

    wprep_kernel<<<NPAD, 256>>>(W1);                 // independent of pool
    pool_kernel<<<BATCH, POOL_T>>>(emb, x, lengths);
    gemm1_fused_kernel<<<dim3(BATCH / BM, NTILES), 256, SMEM_DYN>>>(b1, W2);
    out_reduce_kernel<<<(BATCH * OUTD) / 256, 256>>>(b2, out);
}

// round 13
// speedup vs baseline: 1.2026x; 1.2026x over previous
#include <cuda_runtime.h>
#include <cuda_fp16.h>
#include <math_constants.h>
#include <cstdint>

// Shapes (fixed by the problem)
#define VOCAB   100000
#define DIM     300
#define BATCH   4096
#define SEQ     200
#define KDIM    600      // 2*DIM
#define HIDDEN  1000
#define OUTD    3

// Split-fp16 GEMM1 geometry: A = Ahi + Alo (exact), W ~ fp16(W)
// out = [Ahi | Alo] @ [Wh ; Wh]^T  -> K' = 1216 (38 x 32)
#define KP      1216
#define KC      32       // K elems per SMEM stage
#define NSTAGES (KP / KC)   // 38
#define BM      128
#define BN      128
#define NPAD    1024     // padded N (8 x 128)
#define NTILES  (NPAD / BN)  // 8
#define SKP     40       // smem row stride in fp16 (32 + 8 pad) -> conflict-free ldmatrix

// Scratch (device globals: no allocations allowed)
__device__ __align__(16) __half g_A [BATCH * KP];   // [4096,1216] A' = [Ahi|Alo]
__device__ __align__(16) __half g_Wt[NPAD * KP];    // [1024,1216] W' = [Wh|Wh] (K-major)
__device__ __align__(16) float g_part[NTILES * BATCH * OUTD];  // fused-gemm2 partials

typedef unsigned long long ull;

// ===========================================================================
// Small PTX helpers
// ===========================================================================
__device__ __forceinline__ uint32_t smem_u32(const void* p) {
    uint32_t a;
    asm("{ .reg .u64 t; cvta.to.shared.u64 t, %1; cvt.u32.u64 %0, t; }" : "=r"(a) : "l"(p));
    return a;
}
__device__ __forceinline__ void ldsm_x4(uint32_t& r0, uint32_t& r1, uint32_t& r2,
                                        uint32_t& r3, uint32_t addr) {
    asm volatile("ldmatrix.sync.aligned.m8n8.x4.shared.b16 {%0,%1,%2,%3}, [%4];"
                 : "=r"(r0), "=r"(r1), "=r"(r2), "=r"(r3) : "r"(addr));
}
__device__ __forceinline__ void mma_fp16(float& c0, float& c1, float& c2, float& c3,
                                         uint32_t a0, uint32_t a1, uint32_t a2, uint32_t a3,
                                         uint32_t b0, uint32_t b1) {
    asm volatile("mma.sync.aligned.m16n8k16.row.col.f32.f16.f16.f32 "
                 "{%0,%1,%2,%3}, {%4,%5,%6,%7}, {%8,%9}, {%0,%1,%2,%3};"
                 : "+f"(c0), "+f"(c1), "+f"(c2), "+f"(c3)
                 : "r"(a0), "r"(a1), "r"(a2), "r"(a3), "r"(b0), "r"(b1));
}

// ===========================================================================
// Pool (gather + mean/max) fused with A' fp16 hi/lo emission
// ===========================================================================
__device__ __forceinline__ ull mk_evict_last_policy() {
    ull pol;
    asm("createpolicy.fractional.L2::evict_last.b64 %0, 1.0;" : "=l"(pol));
    return pol;
}
__device__ __forceinline__ float4 ldg_el(const float4* p, ull pol) {
    float4 v;
    asm("ld.global.nc.L2::cache_hint.v4.f32 {%0,%1,%2,%3}, [%4], %5;"
        : "=f"(v.x), "=f"(v.y), "=f"(v.z), "=f"(v.w) : "l"(p), "l"(pol));
    return v;
}

// write 4 floats at A'[row][k..k+3]: hi at k, lo at 600+k (fp16 exact split)
__device__ __forceinline__ void store_hilo4(size_t rowb, int k, float4 v) {
    __half h0 = __float2half(v.x), h1 = __float2half(v.y);
    __half h2 = __float2half(v.z), h3 = __float2half(v.w);
    __half l0 = __float2half(v.x - __half2float(h0));
    __half l1 = __float2half(v.y - __half2float(h1));
    __half l2 = __float2half(v.z - __half2float(h2));
    __half l3 = __float2half(v.w - __half2float(h3));
    *(__half2*)&g_A[rowb + k]           = __halves2half2(h0, h1);
    *(__half2*)&g_A[rowb + k + 2]       = __halves2half2(h2, h3);
    *(__half2*)&g_A[rowb + 600 + k]     = __halves2half2(l0, l1);
    *(__half2*)&g_A[rowb + 600 + k + 2] = __halves2half2(l2, l3);
}

#define D4 (DIM / 4)            // 75 float4 per row
#define POOL_T 160

__global__ __launch_bounds__(POOL_T) void pool_kernel(
    const float* __restrict__ emb,
    const int*   __restrict__ x,
    const int*   __restrict__ lengths)
{
    __shared__ int    sidx[SEQ];
    __shared__ int    slen;
    __shared__ float4 s_sum[2][D4];
    __shared__ float4 s_max[2][D4];

    const int b   = blockIdx.x;
    const int tid = threadIdx.x;

    for (int i = tid; i < SEQ; i += POOL_T) sidx[i] = x[b * SEQ + i];
    if (tid == 0) slen = lengths[b];
    __syncthreads();

    const int len  = slen;
    const int g    = tid / 80;
    const int lane = tid % 80;
    const float NEG_INF = __int_as_float(0xff800000);

    if (lane < D4) {
        const ull pol = mk_evict_last_policy();
        const float4* base = (const float4*)emb + lane;
        float4 sum = make_float4(0.f, 0.f, 0.f, 0.f);
        float4 mx  = make_float4(NEG_INF, NEG_INF, NEG_INF, NEG_INF);
        const int l0 = g * 100;
        #pragma unroll 4
        for (int l = 0; l < 100; ++l) {
            const int tok = l0 + l;
            float4 v = ldg_el(base + (size_t)sidx[tok] * D4, pol);
            sum.x += v.x; sum.y += v.y; sum.z += v.z; sum.w += v.w;
            if (tok < len) {
                mx.x = fmaxf(mx.x, v.x); mx.y = fmaxf(mx.y, v.y);
                mx.z = fmaxf(mx.z, v.z); mx.w = fmaxf(mx.w, v.w);
            }
        }
        s_sum[g][lane] = sum;
        s_max[g][lane] = mx;
    }
    __syncthreads();

    const size_t rowb = (size_t)b * KP;
    if (tid < D4) {
        float4 s0 = s_sum[0][tid], s1 = s_sum[1][tid];
        float4 m0 = s_max[0][tid], m1 = s_max[1][tid];
        const float inv = 1.0f / (float)len;
        float4 mean = make_float4((s0.x + s1.x) * inv, (s0.y + s1.y) * inv,
                                  (s0.z + s1.z) * inv, (s0.w + s1.w) * inv);
        float4 mx   = make_float4(fmaxf(m0.x, m1.x), fmaxf(m0.y, m1.y),
                                  fmaxf(m0.z, m1.z), fmaxf(m0.w, m1.w));
        store_hilo4(rowb, 4 * tid, mean);            // k = d       (hi), 600+d (lo)
        store_hilo4(rowb, DIM + 4 * tid, mx);        // k = 300+d   (hi), 900+d (lo)
    }
    // zero-pad K' [1200,1216)
    if (tid >= 80 && tid < 88) {
        const int k = 1200 + (tid - 80) * 2;
        *(__half2*)&g_A[rowb + k] = __halves2half2(__float2half(0.f), __float2half(0.f));
    }
}

// ===========================================================================
// W' prep: g_Wt[n][k] K-major, [Wh | Wh], rows n>=1000 zero
// ===========================================================================
__global__ __launch_bounds__(256) void wprep_kernel(const float* __restrict__ W1)
{
    const int n = blockIdx.x;                 // 0..1023
    __half* dst = &g_Wt[(size_t)n * KP];
    for (int k = threadIdx.x; k < KP; k += 256) {
        __half o = __float2half(0.f);
        if (n < HIDDEN) {
            if (k < 600) {
                o = __float2half(W1[(size_t)k * HIDDEN + n]);
            } else if (k < 1200) {
                o = __float2half(W1[(size_t)(k - 600) * HIDDEN + n]);
            }
        }
        dst[k] = o;
    }
}

// ===========================================================================
// GEMM1 (fused): partial_out = relu(A' @ W'^T + b1) @ W2, per N-tile.
// 128x128 block, 8 warps (2M x 4N), 64x32 warp tile, KC=32 double-buffered.
// h never hits global memory.
// ===========================================================================
__global__ __launch_bounds__(256) void gemm1_fused_kernel(
    const float* __restrict__ b1,
    const float* __restrict__ W2)
{
    __shared__ __half As[2][BM][SKP];   // 2 x 10240 B
    __shared__ __half Bs[2][BN][SKP];   // 2 x 10240 B
    __shared__ float s_red[4][BM][OUTD];       // 6 KB (per-wn partials)

    const int tid  = threadIdx.x;
    const int warp = tid >> 5;
    const int lane = tid & 31;
    const int wm   = warp >> 2;       // 0..1
    const int wn   = warp & 3;        // 0..3
    const int block_row = blockIdx.x * BM;
    const int block_col = blockIdx.y * BN;

    // Global-load mapping: per tile 128 rows x 32 k = 512 uint4; 2 per thread.
    const int r0 = (tid >> 2);            // u=0 row
    const int c0 = (tid & 3) * 8;         // fp16 col

    const __half* gA0 = &g_A [(size_t)(block_row + r0)      * KP + c0];
    const __half* gA1 = &g_A [(size_t)(block_row + r0 + 64) * KP + c0];
    const __half* gB0 = &g_Wt[(size_t)(block_col + r0)      * KP + c0];
    const __half* gB1 = &g_Wt[(size_t)(block_col + r0 + 64) * KP + c0];

    // ldmatrix per-lane coordinates
    const int a_m = lane & 15;                          // row within 16
    const int a_k = (lane >> 4) << 3;                   // 0 or 8
    const int b_n = ((lane >> 4) << 3) + (lane & 7);    // row within 16 (n)
    const int b_k = lane & 8;                           // 0 or 8

    float acc[4][4][4];
    #pragma unroll
    for (int i = 0; i < 4; ++i)
        #pragma unroll
        for (int j = 0; j < 4; ++j)
            #pragma unroll
            for (int e = 0; e < 4; ++e) acc[i][j][e] = 0.0f;

    // Preload stage 0
    {
        *(uint4*)&As[0][r0     ][c0] = *(const uint4*)gA0;
        *(uint4*)&As[0][r0 + 64][c0] = *(const uint4*)gA1;
        *(uint4*)&Bs[0][r0     ][c0] = *(const uint4*)gB0;
        *(uint4*)&Bs[0][r0 + 64][c0] = *(const uint4*)gB1;
    }
    __syncthreads();

    for (int s = 0; s < NSTAGES; ++s) {
        const int buf = s & 1;
        uint4 pa0, pa1, pb0, pb1;
        const bool more = (s + 1 < NSTAGES);
        if (more) {
            const size_t koff = (size_t)(s + 1) * KC;
            pa0 = *(const uint4*)(gA0 + koff);
            pa1 = *(const uint4*)(gA1 + koff);
            pb0 = *(const uint4*)(gB0 + koff);
            pb1 = *(const uint4*)(gB1 + koff);
        }

        #pragma unroll
        for (int q = 0; q < 2; ++q) {                 // two k16 steps
            const int kq = q * 16;
            uint32_t a[4][4];
            #pragma unroll
            for (int i = 0; i < 4; ++i) {
                const uint32_t addr = smem_u32(
                    &As[buf][wm * 64 + i * 16 + a_m][kq + a_k]);
                ldsm_x4(a[i][0], a[i][1], a[i][2], a[i][3], addr);
            }
            uint32_t bfr[4][2];
            #pragma unroll
            for (int p = 0; p < 2; ++p) {             // pairs of n8 tiles
                const uint32_t addr = smem_u32(
                    &Bs[buf][wn * 32 + p * 16 + b_n][kq + b_k]);
                uint32_t t0, t1, t2, t3;
                ldsm_x4(t0, t1, t2, t3, addr);
                bfr[p * 2 + 0][0] = t0; bfr[p * 2 + 0][1] = t1;
                bfr[p * 2 + 1][0] = t2; bfr[p * 2 + 1][1] = t3;
            }
            #pragma unroll
            for (int i = 0; i < 4; ++i)
                #pragma unroll
                for (int j = 0; j < 4; ++j)
                    mma_fp16(acc[i][j][0], acc[i][j][1], acc[i][j][2], acc[i][j][3],
                             a[i][0], a[i][1], a[i][2], a[i][3],
                             bfr[j][0], bfr[j][1]);
        }

        if (more) {
            const int nb = buf ^ 1;
            *(uint4*)&As[nb][r0     ][c0] = pa0;
            *(uint4*)&As[nb][r0 + 64][c0] = pa1;
            *(uint4*)&Bs[nb][r0     ][c0] = pb0;
            *(uint4*)&Bs[nb][r0 + 64][c0] = pb1;
        }
        __syncthreads();
    }

    // ---- Fused epilogue: p[m][c] = sum_n relu(acc + b1[n]) * W2[n][c] ----
    const int mq = lane >> 2;            // 0..7
    const int nq = (lane & 3) * 2;       // 0,2,4,6

    float part[8][OUTD];                 // r = i*2 + e_hi -> m rows
    #pragma unroll
    for (int r = 0; r < 8; ++r)
        #pragma unroll
        for (int c = 0; c < OUTD; ++c) part[r][c] = 0.0f;

    #pragma unroll
    for (int j = 0; j < 4; ++j) {
        const int n0 = block_col + wn * 32 + j * 8 + nq;   // even; n1 = n0+1
        float bn0 = 0.f, bn1 = 0.f;
        float w0[OUTD] = {0.f, 0.f, 0.f}, w1[OUTD] = {0.f, 0.f, 0.f};
        if (n0 < HIDDEN) {
            bn0 = b1[n0]; bn1 = b1[n0 + 1];
            #pragma unroll
            for (int c = 0; c < OUTD; ++c) {
                w0[c] = W2[n0 * OUTD + c];
                w1[c] = W2[(n0 + 1) * OUTD + c];
            }
        }
        #pragma unroll
        for (int i = 0; i < 4; ++i) {
            const float h00 = fmaxf(acc[i][j][0] + bn0, 0.0f);
            const float h01 = fmaxf(acc[i][j][1] + bn1, 0.0f);
            const float h10 = fmaxf(acc[i][j][2] + bn0, 0.0f);
            const float h11 = fmaxf(acc[i][j][3] + bn1, 0.0f);
            #pragma unroll
            for (int c = 0; c < OUTD; ++c) {
                part[i * 2 + 0][c] = fmaf(h00, w0[c], fmaf(h01, w1[c], part[i * 2 + 0][c]));
                part[i * 2 + 1][c] = fmaf(h10, w0[c], fmaf(h11, w1[c], part[i * 2 + 1][c]));
            }
        }
    }

    // reduce across the 4 lanes (nq groups) sharing each m-row (deterministic)
    #pragma unroll
    for (int r = 0; r < 8; ++r)
        #pragma unroll
        for (int c = 0; c < OUTD; ++c) {
            float v = part[r][c];
            v += __shfl_xor_sync(0xFFFFFFFFu, v, 1);
            v += __shfl_xor_sync(0xFFFFFFFFu, v, 2);
            part[r][c] = v;
        }

    if ((lane & 3) == 0) {
        #pragma unroll
        for (int r = 0; r < 8; ++r) {
            const int row = wm * 64 + (r >> 1) * 16 + mq + (r & 1) * 8;
            #pragma unroll
            for (int c = 0; c < OUTD; ++c) s_red[wn][row][c] = part[r][c];
        }
    }
    __syncthreads();

    // sum the 4 wn slices; one (row, c) per thread
    for (int idx = tid; idx < BM * OUTD; idx += 256) {
        const int row = idx / OUTD, c = idx % OUTD;
        const float v = s_red[0][row][c] + s_red[1][row][c]
                      + s_red[2][row][c] + s_red[3][row][c];
        g_part[((size_t)blockIdx.y * BATCH + (block_row + row)) * OUTD + c] = v;
    }
}

// ===========================================================================
// Final reduce: out[m][c] = b2[c] + sum_z g_part[z][m][c]   (fixed order)
// ===========================================================================
__global__ __launch_bounds__(256) void out_reduce_kernel(
    const float* __restrict__ b2,
    float* __restrict__ out)
{
    const int m = blockIdx.x * 256 + threadIdx.x;
    float a0 = b2[0], a1 = b2[1], a2 = b2[2];
    #pragma unroll
    for (int z = 0; z < NTILES; ++z) {
        const size_t o = ((size_t)z * BATCH + m) * OUTD;
        a0 += g_part[o + 0]; a1 += g_part[o + 1]; a2 += g_part[o + 2];
    }
    out[m * 3 + 0] = a0; out[m * 3 + 1] = a1; out[m * 3 + 2] = a2;
}

// ===========================================================================
// Launch. Input order (metadata): emb_table, W1, b1, W2, b2, x, lengths.
// ===========================================================================
extern "C" void kernel_launch(void* const* d_in, const int* in_sizes, int n_in,
                              void* d_out, int out_size)
{
    const float* emb     = (const float*)d_in[0];
    const float* W1      = (const float*)d_in[1];
    const float* b1      = (const float*)d_in[2];
    const float* W2      = (const float*)d_in[3];
    const float* b2      = (const float*)d_in[4];
    const int*   x       = (const int*)  d_in[5];
    const int*   lengths = (const int*)  d_in[6];
    float*       out     = (float*)d_out;

    wprep_kernel<<<NPAD, 256>>>(W1);                 // independent of pool
    pool_kernel<<<BATCH, POOL_T>>>(emb, x, lengths);
    gemm1_fused_kernel<<<dim3(BATCH / BM, NTILES), 256>>>(b1, W2);  // (32, 8)
    out_reduce_kernel<<<BATCH / 256, 256>>>(b2, out);
}